// round 16
// baseline (speedup 1.0000x reference)
#include <cuda_runtime.h>
#include <cstdint>
#include <cstddef>

// ---------------------------------------------------------------------------
// MPConv fused GNN edge-MLP + scatter on GB300 (sm_103a)
// R16 = R15 (proven 333.4us) + cp.async smem gather prefetch: A[i]/B[j]
//       rows prefetched into shared during GEMM1 (latency fully covered),
//       epilogue gathers become LDS. 91.6KB smem -> 2 CTAs/SM.
// ---------------------------------------------------------------------------

#define NODES_MAX 100000
#define E_TILE    128
#define NTHREADS  256

typedef unsigned long long ull_t;

__device__ __align__(16) float g_AB[(size_t)NODES_MAX * 128];   // A||B per node
__device__ __align__(16) float g_G[(size_t)NODES_MAX * 64];     // scattered g sums
__device__ __align__(16) float g_degf[NODES_MAX];               // edge counts
__device__ int g_idx64;

// Branch-free GELU: 0.5v(1+erf(v/sqrt2)), erf via A&S 7.1.26 (|err|<=1.5e-7)
__device__ __forceinline__ float gelu_exact(float v) {
    float z = v * 0.70710678118654752440f;
    float a = fabsf(z);
    float r;
    asm("rcp.approx.f32 %0, %1;" : "=f"(r) : "f"(fmaf(0.3275911f, a, 1.0f)));
    float u = fmaf(r, 1.061405429f, -1.453152027f);
    u = fmaf(r, u, 1.421413741f);
    u = fmaf(r, u, -0.284496736f);
    u = fmaf(r, u, 0.254829592f);
    float poly = u * r;
    float e;
    asm("ex2.approx.f32 %0, %1;" : "=f"(e) : "f"(z * z * -1.4426950408889634f));
    float erf_abs = fmaf(-poly, e, 1.0f);
    float erf = __int_as_float(__float_as_int(erf_abs) |
                               (__float_as_int(z) & 0x80000000));
    float hv = 0.5f * v;
    return fmaf(hv, erf, hv);
}

__device__ __forceinline__ void fma2(ull_t& d, ull_t a, ull_t b) {
    asm("fma.rn.f32x2 %0, %1, %2, %0;" : "+l"(d) : "l"(a), "l"(b));
}
__device__ __forceinline__ ull_t add2(ull_t a, ull_t b) {
    ull_t d;
    asm("add.rn.f32x2 %0, %1, %2;" : "=l"(d) : "l"(a), "l"(b));
    return d;
}
__device__ __forceinline__ ull_t mul2(ull_t a, ull_t b) {
    ull_t d;
    asm("mul.rn.f32x2 %0, %1, %2;" : "=l"(d) : "l"(a), "l"(b));
    return d;
}
#define UNPK(lo, hi, v) asm("mov.b64 {%0,%1}, %2;" : "=f"(lo), "=f"(hi) : "l"(v))
#define DUP(d, f)       asm("mov.b64 %0, {%1, %1};" : "=l"(d) : "f"(f))
#define PACK2(d, lo, hi) asm("mov.b64 %0, {%1, %2};" : "=l"(d) : "f"(lo), "f"(hi))

#define CP_ASYNC16(smem_u32, gptr)                                             \
    asm volatile("cp.async.cg.shared.global [%0], [%1], 16;"                   \
                 :: "r"(smem_u32), "l"(gptr) : "memory")

// ---------------------------------------------------------------------------
// parallel dtype detect: int32 data misread as int64 escapes [0,N) w.h.p.
__global__ void detect_idx_kernel(const void* edge_index, int N) {
    __shared__ int s_bad;
    int t = threadIdx.x;
    if (t == 0) s_bad = 0;
    __syncthreads();
    long long v = ((const long long*)edge_index)[t];
    if (v < 0 || v >= (long long)N) atomicOr(&s_bad, 1);
    __syncthreads();
    if (t == 0) g_idx64 = !s_bad;
}

__device__ __forceinline__ int load_edge_idx(const void* ei, long long pos, int idx64) {
    if (idx64) return (int)((const long long*)ei)[pos];
    return ((const int*)ei)[pos];
}

// ---------------------------------------------------------------------------
// Precompute g_AB (R14 FFMA2, node-pair packing) + zero G/deg slice.
// dyn smem: xT[64][66] (16896) + Wc[64][128] (32768) = 49664 B
__global__ void __launch_bounds__(NTHREADS, 2)
precompute_kernel(const float* __restrict__ x,
                  const float* __restrict__ W1,
                  const float* __restrict__ b1,
                  int N) {
    extern __shared__ float sm[];
    float* xT = sm;                  // [k][node], stride 66
    float* Wc = sm + 64 * 66;        // [k][c] 64x128

    int t = threadIdx.x;
    int n_base = blockIdx.x * 64;

    {
        float4 z4 = make_float4(0.f, 0.f, 0.f, 0.f);
#pragma unroll
        for (int it = 0; it < 4; ++it) {
            int idx = t + it * NTHREADS;
            int node = idx >> 4, q = idx & 15;
            int gn = n_base + node;
            if (gn < N) ((float4*)g_G)[(size_t)gn * 16 + q] = z4;
        }
        if (t < 64 && n_base + t < N) g_degf[n_base + t] = 0.f;
    }

#pragma unroll
    for (int it = 0; it < 32; ++it) {
        int idx = t + it * NTHREADS;
        int k = idx >> 7, c = idx & 127;
        Wc[idx] = (c < 64) ? W1[k * 64 + c] : W1[(64 + k) * 64 + (c - 64)];
    }
#pragma unroll
    for (int it = 0; it < 16; ++it) {
        int idx = t + it * NTHREADS;
        int node = idx >> 6, k = idx & 63;
        int gn = n_base + node;
        xT[k * 66 + node] = (gn < N) ? x[(size_t)gn * 64 + k] : 0.f;
    }
    __syncthreads();

    int tx = t & 31, ty = t >> 5;
    int c0 = tx * 4, n0 = ty * 8;

    ull_t acc[16];
    {
        ull_t binit[4];
        if (c0 < 64) {
            float4 bv = *(const float4*)&b1[c0];
            DUP(binit[0], bv.x); DUP(binit[1], bv.y);
            DUP(binit[2], bv.z); DUP(binit[3], bv.w);
        } else {
            binit[0] = binit[1] = binit[2] = binit[3] = 0ull;
        }
#pragma unroll
        for (int p = 0; p < 4; ++p)
#pragma unroll
            for (int c = 0; c < 4; ++c) acc[p * 4 + c] = binit[c];
    }

#pragma unroll 4
    for (int k = 0; k < 64; ++k) {
        float4 w = *(const float4*)&Wc[k * 128 + c0];
        ull_t W0, W1r, W2r, W3r;
        DUP(W0, w.x); DUP(W1r, w.y); DUP(W2r, w.z); DUP(W3r, w.w);
        const ull_t* xp = (const ull_t*)&xT[k * 66 + n0];
        ull_t X0 = xp[0], X1 = xp[1], X2 = xp[2], X3 = xp[3];
        fma2(acc[ 0], X0, W0); fma2(acc[ 1], X0, W1r);
        fma2(acc[ 2], X0, W2r); fma2(acc[ 3], X0, W3r);
        fma2(acc[ 4], X1, W0); fma2(acc[ 5], X1, W1r);
        fma2(acc[ 6], X1, W2r); fma2(acc[ 7], X1, W3r);
        fma2(acc[ 8], X2, W0); fma2(acc[ 9], X2, W1r);
        fma2(acc[10], X2, W2r); fma2(acc[11], X2, W3r);
        fma2(acc[12], X3, W0); fma2(acc[13], X3, W1r);
        fma2(acc[14], X3, W2r); fma2(acc[15], X3, W3r);
    }

#pragma unroll
    for (int p = 0; p < 4; ++p) {
        float lo0, hi0, lo1, hi1, lo2, hi2, lo3, hi3;
        UNPK(lo0, hi0, acc[p * 4 + 0]);
        UNPK(lo1, hi1, acc[p * 4 + 1]);
        UNPK(lo2, hi2, acc[p * 4 + 2]);
        UNPK(lo3, hi3, acc[p * 4 + 3]);
        int gn0 = n_base + n0 + 2 * p;
        if (gn0 < N)
            *(float4*)&g_AB[(size_t)gn0 * 128 + c0] = make_float4(lo0, lo1, lo2, lo3);
        if (gn0 + 1 < N)
            *(float4*)&g_AB[(size_t)(gn0 + 1) * 128 + c0] = make_float4(hi0, hi1, hi2, hi3);
    }
}

// ---------------------------------------------------------------------------
// Edge kernel. 128 edges/block, 256 threads, 4ch x 8edge per thread.
// cp.async prefetch of A[i]/B[j] gathers into smem, covered by GEMM1.
// dyn smem (91648 B):
//   iidx[128] @0, jidx[128] @512
//   W1p [32][64] f32 raw @1024   (8192)
//   eaT [32][132] f32    @9216   (16896)
//   gA  [128][64] f32    @26112  (32768)   A[i] rows, 256B per edge
//   gB  [128][64] f32    @58880  (32768)   B[j] rows
__global__ void __launch_bounds__(NTHREADS, 2)
edge_kernel(const void* __restrict__ edge_index,
            const float* __restrict__ edge_attr,
            const float* __restrict__ W1,
            const float* __restrict__ gamma,
            const float* __restrict__ beta,
            int E) {
    extern __shared__ char smraw[];
    int*   iidx = (int*)smraw;
    int*   jidx = iidx + 128;
    float* W1p  = (float*)(smraw + 1024);
    float* eaT  = (float*)(smraw + 9216);
    float* gA   = (float*)(smraw + 26112);
    float* gB   = (float*)(smraw + 58880);

    int t = threadIdx.x;
    long long e_base = (long long)blockIdx.x * E_TILE;
    int idx64 = g_idx64;

    if (t < 128) iidx[t] = load_edge_idx(edge_index, e_base + t, idx64);
    else         jidx[t - 128] = load_edge_idx(edge_index, (long long)E + e_base + (t - 128), idx64);

    // W1p: raw copy of W1 rows 128..159 (2048 floats = 512 float4)
    {
        const float4* src = (const float4*)(W1 + 128 * 64);
        float4* dst = (float4*)W1p;
        dst[t]       = src[t];
        dst[t + 256] = src[t + 256];
    }
    // edge_attr transposed: eaT[k][e], stride 132
    {
        const float4* ea4 = (const float4*)edge_attr;
#pragma unroll
        for (int it = 0; it < 4; ++it) {
            int slot = t + it * NTHREADS;           // 0..1023
            int e = slot >> 3, q = slot & 7;
            float4 v = ea4[e_base * 8 + slot];
            int k = q * 4;
            eaT[(k + 0) * 132 + e] = v.x;
            eaT[(k + 1) * 132 + e] = v.y;
            eaT[(k + 2) * 132 + e] = v.z;
            eaT[(k + 3) * 132 + e] = v.w;
        }
    }
    __syncthreads();

    int tx = t & 15, ty = t >> 4;
    int c0 = tx * 4, e0 = ty * 8;

    // -------- issue gather prefetches (covered by GEMM1 below) --------
    // Each thread fetches ITS OWN consumption: 8 edges x (A chunk + B chunk).
    {
        unsigned sA = (unsigned)__cvta_generic_to_shared(gA) + (e0 * 64 + tx * 4) * 4;
        unsigned sB = (unsigned)__cvta_generic_to_shared(gB) + (e0 * 64 + tx * 4) * 4;
#pragma unroll
        for (int r = 0; r < 8; ++r) {
            int e = e0 + r;
            const float* pa = g_AB + (size_t)iidx[e] * 128 + c0;         // A part
            const float* pb = g_AB + (size_t)jidx[e] * 128 + 64 + c0;    // B part
            CP_ASYNC16(sA + r * 256, pa);
            CP_ASYNC16(sB + r * 256, pb);
        }
        asm volatile("cp.async.commit_group;" ::: "memory");
    }

    // acc[c*4+p]: channel c (0..3), edge-pair p (0..3), lanes = (e0+2p, e0+2p+1)
    ull_t acc[16];
#pragma unroll
    for (int i = 0; i < 16; ++i) acc[i] = 0ull;

    // -------- GEMM1: h = ea @ W1c (raw weight LDS.128 + reg dup) --------
#pragma unroll 4
    for (int kk = 0; kk < 32; ++kk) {
        float4 w = *(const float4*)&W1p[kk * 64 + c0];
        ull_t W0, W1r, W2r, W3r;
        DUP(W0, w.x); DUP(W1r, w.y); DUP(W2r, w.z); DUP(W3r, w.w);
        const float* ap = eaT + kk * 132 + e0;
        ulonglong2 A01 = *(const ulonglong2*)(ap);
        ulonglong2 A23 = *(const ulonglong2*)(ap + 4);
        fma2(acc[ 0], A01.x, W0);  fma2(acc[ 1], A01.y, W0);
        fma2(acc[ 2], A23.x, W0);  fma2(acc[ 3], A23.y, W0);
        fma2(acc[ 4], A01.x, W1r); fma2(acc[ 5], A01.y, W1r);
        fma2(acc[ 6], A23.x, W1r); fma2(acc[ 7], A23.y, W1r);
        fma2(acc[ 8], A01.x, W2r); fma2(acc[ 9], A01.y, W2r);
        fma2(acc[10], A23.x, W2r); fma2(acc[11], A23.y, W2r);
        fma2(acc[12], A01.x, W3r); fma2(acc[13], A01.y, W3r);
        fma2(acc[14], A23.x, W3r); fma2(acc[15], A23.y, W3r);
    }

    // wait for this thread's prefetched gathers (self-consumed: no syncthreads)
    asm volatile("cp.async.wait_group 0;" ::: "memory");

    // -------- epilogue, pair-by-pair, packed (gathers now LDS) --------
    float4 gmv = *(const float4*)&gamma[c0];
    float4 btv = *(const float4*)&beta[c0];
    ull_t GM0, GM1, GM2, GM3, BT0, BT1, BT2, BT3;
    DUP(GM0, gmv.x); DUP(GM1, gmv.y); DUP(GM2, gmv.z); DUP(GM3, gmv.w);
    DUP(BT0, btv.x); DUP(BT1, btv.y); DUP(BT2, btv.z); DUP(BT3, btv.w);

#pragma unroll
    for (int p = 0; p < 4; ++p) {
        int ea = e0 + 2 * p, eb = ea + 1;

        float4 Aa = *(const float4*)&gA[ea * 64 + c0];
        float4 Ba = *(const float4*)&gB[ea * 64 + c0];
        float4 Ab = *(const float4*)&gA[eb * 64 + c0];
        float4 Bb = *(const float4*)&gB[eb * 64 + c0];

        ull_t g0, g1, g2, g3;
        PACK2(g0, Aa.x + Ba.x, Ab.x + Bb.x);
        PACK2(g1, Aa.y + Ba.y, Ab.y + Bb.y);
        PACK2(g2, Aa.z + Ba.z, Ab.z + Bb.z);
        PACK2(g3, Aa.w + Ba.w, Ab.w + Bb.w);

        ull_t h0 = add2(acc[0 * 4 + p], g0);
        ull_t h1 = add2(acc[1 * 4 + p], g1);
        ull_t h2 = add2(acc[2 * 4 + p], g2);
        ull_t h3 = add2(acc[3 * 4 + p], g3);

        ull_t s_pk = add2(add2(h0, h1), add2(h2, h3));
        ull_t q_pk = 0ull;
        fma2(q_pk, h0, h0); fma2(q_pk, h1, h1);
        fma2(q_pk, h2, h2); fma2(q_pk, h3, h3);

        float sa, sb, qa, qb;
        UNPK(sa, sb, s_pk);
        UNPK(qa, qb, q_pk);
#pragma unroll
        for (int off = 8; off >= 1; off >>= 1) {
            sa += __shfl_xor_sync(0xffffffffu, sa, off, 16);
            sb += __shfl_xor_sync(0xffffffffu, sb, off, 16);
            qa += __shfl_xor_sync(0xffffffffu, qa, off, 16);
            qb += __shfl_xor_sync(0xffffffffu, qb, off, 16);
        }
        float mua = sa * (1.0f / 64.0f);
        float mub = sb * (1.0f / 64.0f);
        float ra  = rsqrtf(qa * (1.0f / 64.0f) - mua * mua + 1e-5f);
        float rb  = rsqrtf(qb * (1.0f / 64.0f) - mub * mub + 1e-5f);

        ull_t NMU, RR;
        PACK2(NMU, -mua, -mub);
        PACK2(RR, ra, rb);

        ull_t y0 = BT0; fma2(y0, mul2(add2(h0, NMU), RR), GM0);
        ull_t y1 = BT1; fma2(y1, mul2(add2(h1, NMU), RR), GM1);
        ull_t y2 = BT2; fma2(y2, mul2(add2(h2, NMU), RR), GM2);
        ull_t y3 = BT3; fma2(y3, mul2(add2(h3, NMU), RR), GM3);

        float va0, vb0, va1, vb1, va2, vb2, va3, vb3;
        UNPK(va0, vb0, y0);
        UNPK(va1, vb1, y1);
        UNPK(va2, vb2, y2);
        UNPK(va3, vb3, y3);

        va0 = gelu_exact(va0); va1 = gelu_exact(va1);
        va2 = gelu_exact(va2); va3 = gelu_exact(va3);
        vb0 = gelu_exact(vb0); vb1 = gelu_exact(vb1);
        vb2 = gelu_exact(vb2); vb3 = gelu_exact(vb3);

        {
            int vja = jidx[ea];
            float* pa = g_G + (size_t)vja * 64 + c0;
            asm volatile("red.global.add.v4.f32 [%0], {%1,%2,%3,%4};"
                         :: "l"(pa), "f"(va0), "f"(va1), "f"(va2), "f"(va3) : "memory");
            int vjb = jidx[eb];
            float* pb = g_G + (size_t)vjb * 64 + c0;
            asm volatile("red.global.add.v4.f32 [%0], {%1,%2,%3,%4};"
                         :: "l"(pb), "f"(vb0), "f"(vb1), "f"(vb2), "f"(vb3) : "memory");
            if (tx == 0) {
                asm volatile("red.global.add.f32 [%0], %1;"
                             :: "l"(g_degf + vja), "f"(1.0f) : "memory");
                asm volatile("red.global.add.f32 [%0], %1;"
                             :: "l"(g_degf + vjb), "f"(1.0f) : "memory");
            }
        }
    }
}

// ---------------------------------------------------------------------------
// Node kernel (R14 FFMA2, node-pair packing).
// dyn smem: GT[64][66] (16896) + W2s[64][64] (16384) = 33280 B
__global__ void __launch_bounds__(NTHREADS, 2)
node_kernel(const float* __restrict__ W2,
            const float* __restrict__ b2,
            float* __restrict__ out,
            int N) {
    extern __shared__ float sm[];
    float* GT  = sm;                  // [k][node], stride 66
    float* W2s = sm + 64 * 66;        // [k][c] 64x64

    int t = threadIdx.x;
    int n_base = blockIdx.x * 64;

#pragma unroll
    for (int it = 0; it < 16; ++it) {
        int idx = t + it * NTHREADS;
        int node = idx >> 6, k = idx & 63;
        int gn = n_base + node;
        GT[k * 66 + node] = (gn < N) ? g_G[(size_t)gn * 64 + k] : 0.f;
        W2s[idx] = W2[idx];
    }
    __syncthreads();

    int tx = t & 15, ty = t >> 4;
    int c0 = tx * 4, n0 = ty * 4;

    ull_t acc[8];
#pragma unroll
    for (int i = 0; i < 8; ++i) acc[i] = 0ull;

#pragma unroll 4
    for (int k = 0; k < 64; ++k) {
        float4 w = *(const float4*)&W2s[k * 64 + c0];
        ull_t W0, W1r, W2r, W3r;
        DUP(W0, w.x); DUP(W1r, w.y); DUP(W2r, w.z); DUP(W3r, w.w);
        const ull_t* gp = (const ull_t*)&GT[k * 66 + n0];
        ull_t X0 = gp[0], X1 = gp[1];
        fma2(acc[0], X0, W0); fma2(acc[1], X0, W1r);
        fma2(acc[2], X0, W2r); fma2(acc[3], X0, W3r);
        fma2(acc[4], X1, W0); fma2(acc[5], X1, W1r);
        fma2(acc[6], X1, W2r); fma2(acc[7], X1, W3r);
    }

    float4 b2v = *(const float4*)&b2[c0];
    ull_t B0, B1, B2, B3;
    DUP(B0, b2v.x); DUP(B1, b2v.y); DUP(B2, b2v.z); DUP(B3, b2v.w);

#pragma unroll
    for (int p = 0; p < 2; ++p) {
        int gn0 = n_base + n0 + 2 * p;
        float d0 = (gn0 < N)     ? g_degf[gn0]     : 0.f;
        float d1 = (gn0 + 1 < N) ? g_degf[gn0 + 1] : 0.f;
        ull_t D; PACK2(D, d0, d1);
        ull_t v0 = acc[p * 4 + 0], v1 = acc[p * 4 + 1];
        ull_t v2 = acc[p * 4 + 2], v3 = acc[p * 4 + 3];
        fma2(v0, D, B0); fma2(v1, D, B1);
        fma2(v2, D, B2); fma2(v3, D, B3);
        float lo0, hi0, lo1, hi1, lo2, hi2, lo3, hi3;
        UNPK(lo0, hi0, v0); UNPK(lo1, hi1, v1);
        UNPK(lo2, hi2, v2); UNPK(lo3, hi3, v3);
        if (gn0 < N)
            *(float4*)&out[(size_t)gn0 * 64 + c0] = make_float4(lo0, lo1, lo2, lo3);
        if (gn0 + 1 < N)
            *(float4*)&out[(size_t)(gn0 + 1) * 64 + c0] = make_float4(hi0, hi1, hi2, hi3);
    }
}

// ---------------------------------------------------------------------------
extern "C" void kernel_launch(void* const* d_in, const int* in_sizes, int n_in,
                              void* d_out, int out_size) {
    const float* x          = (const float*)d_in[0];
    const void*  edge_index = d_in[1];
    const float* edge_attr  = (const float*)d_in[2];
    const float* W1         = (const float*)d_in[3];
    const float* b1         = (const float*)d_in[4];
    const float* gamma      = (const float*)d_in[5];
    const float* beta       = (const float*)d_in[6];
    const float* W2         = (const float*)d_in[7];
    const float* b2         = (const float*)d_in[8];
    float*       out        = (float*)d_out;

    int N = in_sizes[0] / 64;     // 100000
    int E = in_sizes[2] / 32;     // 1600000

    const int SM_PRE  = (64 * 66 + 64 * 128) * 4;   // 49664
    const int SM_EDGE = 91648;
    const int SM_NODE = (64 * 66 + 64 * 64) * 4;    // 33280
    cudaFuncSetAttribute(precompute_kernel, cudaFuncAttributeMaxDynamicSharedMemorySize, SM_PRE);
    cudaFuncSetAttribute(edge_kernel,       cudaFuncAttributeMaxDynamicSharedMemorySize, SM_EDGE);
    cudaFuncSetAttribute(node_kernel,       cudaFuncAttributeMaxDynamicSharedMemorySize, SM_NODE);

    detect_idx_kernel<<<1, 128>>>(edge_index, N);
    precompute_kernel<<<(N + 63) / 64, NTHREADS, SM_PRE>>>(x, W1, b1, N);
    edge_kernel<<<E / E_TILE, NTHREADS, SM_EDGE>>>(edge_index, edge_attr, W1,
                                                   gamma, beta, E);
    node_kernel<<<(N + 63) / 64, NTHREADS, SM_NODE>>>(W2, b2, out, N);
}

// round 17
// speedup vs baseline: 1.0490x; 1.0490x over previous
#include <cuda_runtime.h>
#include <cstdint>
#include <cstddef>

// ---------------------------------------------------------------------------
// MPConv fused GNN edge-MLP + scatter on GB300 (sm_103a)
// R17 = R15 (proven 333.4us) + HALF cp.async gather prefetch (pairs 2-3 only,
//       32KB cache) keeping 3 CTAs/SM. Pairs 0-1 keep direct LDG gathers.
// ---------------------------------------------------------------------------

#define NODES_MAX 100000
#define E_TILE    128
#define NTHREADS  256

typedef unsigned long long ull_t;

__device__ __align__(16) float g_AB[(size_t)NODES_MAX * 128];   // A||B per node
__device__ __align__(16) float g_G[(size_t)NODES_MAX * 64];     // scattered g sums
__device__ __align__(16) float g_degf[NODES_MAX];               // edge counts
__device__ int g_idx64;

// Branch-free GELU: 0.5v(1+erf(v/sqrt2)), erf via A&S 7.1.26 (|err|<=1.5e-7)
__device__ __forceinline__ float gelu_exact(float v) {
    float z = v * 0.70710678118654752440f;
    float a = fabsf(z);
    float r;
    asm("rcp.approx.f32 %0, %1;" : "=f"(r) : "f"(fmaf(0.3275911f, a, 1.0f)));
    float u = fmaf(r, 1.061405429f, -1.453152027f);
    u = fmaf(r, u, 1.421413741f);
    u = fmaf(r, u, -0.284496736f);
    u = fmaf(r, u, 0.254829592f);
    float poly = u * r;
    float e;
    asm("ex2.approx.f32 %0, %1;" : "=f"(e) : "f"(z * z * -1.4426950408889634f));
    float erf_abs = fmaf(-poly, e, 1.0f);
    float erf = __int_as_float(__float_as_int(erf_abs) |
                               (__float_as_int(z) & 0x80000000));
    float hv = 0.5f * v;
    return fmaf(hv, erf, hv);
}

__device__ __forceinline__ void fma2(ull_t& d, ull_t a, ull_t b) {
    asm("fma.rn.f32x2 %0, %1, %2, %0;" : "+l"(d) : "l"(a), "l"(b));
}
__device__ __forceinline__ ull_t add2(ull_t a, ull_t b) {
    ull_t d;
    asm("add.rn.f32x2 %0, %1, %2;" : "=l"(d) : "l"(a), "l"(b));
    return d;
}
__device__ __forceinline__ ull_t mul2(ull_t a, ull_t b) {
    ull_t d;
    asm("mul.rn.f32x2 %0, %1, %2;" : "=l"(d) : "l"(a), "l"(b));
    return d;
}
#define UNPK(lo, hi, v) asm("mov.b64 {%0,%1}, %2;" : "=f"(lo), "=f"(hi) : "l"(v))
#define DUP(d, f)       asm("mov.b64 %0, {%1, %1};" : "=l"(d) : "f"(f))
#define PACK2(d, lo, hi) asm("mov.b64 %0, {%1, %2};" : "=l"(d) : "f"(lo), "f"(hi))

#define CP_ASYNC16(smem_u32, gptr)                                             \
    asm volatile("cp.async.cg.shared.global [%0], [%1], 16;"                   \
                 :: "r"(smem_u32), "l"(gptr) : "memory")

// ---------------------------------------------------------------------------
// parallel dtype detect: int32 data misread as int64 escapes [0,N) w.h.p.
__global__ void detect_idx_kernel(const void* edge_index, int N) {
    __shared__ int s_bad;
    int t = threadIdx.x;
    if (t == 0) s_bad = 0;
    __syncthreads();
    long long v = ((const long long*)edge_index)[t];
    if (v < 0 || v >= (long long)N) atomicOr(&s_bad, 1);
    __syncthreads();
    if (t == 0) g_idx64 = !s_bad;
}

__device__ __forceinline__ int load_edge_idx(const void* ei, long long pos, int idx64) {
    if (idx64) return (int)((const long long*)ei)[pos];
    return ((const int*)ei)[pos];
}

// ---------------------------------------------------------------------------
// Precompute g_AB (R14 FFMA2, node-pair packing) + zero G/deg slice.
// dyn smem: xT[64][66] (16896) + Wc[64][128] (32768) = 49664 B
__global__ void __launch_bounds__(NTHREADS, 2)
precompute_kernel(const float* __restrict__ x,
                  const float* __restrict__ W1,
                  const float* __restrict__ b1,
                  int N) {
    extern __shared__ float sm[];
    float* xT = sm;                  // [k][node], stride 66
    float* Wc = sm + 64 * 66;        // [k][c] 64x128

    int t = threadIdx.x;
    int n_base = blockIdx.x * 64;

    {
        float4 z4 = make_float4(0.f, 0.f, 0.f, 0.f);
#pragma unroll
        for (int it = 0; it < 4; ++it) {
            int idx = t + it * NTHREADS;
            int node = idx >> 4, q = idx & 15;
            int gn = n_base + node;
            if (gn < N) ((float4*)g_G)[(size_t)gn * 16 + q] = z4;
        }
        if (t < 64 && n_base + t < N) g_degf[n_base + t] = 0.f;
    }

#pragma unroll
    for (int it = 0; it < 32; ++it) {
        int idx = t + it * NTHREADS;
        int k = idx >> 7, c = idx & 127;
        Wc[idx] = (c < 64) ? W1[k * 64 + c] : W1[(64 + k) * 64 + (c - 64)];
    }
#pragma unroll
    for (int it = 0; it < 16; ++it) {
        int idx = t + it * NTHREADS;
        int node = idx >> 6, k = idx & 63;
        int gn = n_base + node;
        xT[k * 66 + node] = (gn < N) ? x[(size_t)gn * 64 + k] : 0.f;
    }
    __syncthreads();

    int tx = t & 31, ty = t >> 5;
    int c0 = tx * 4, n0 = ty * 8;

    ull_t acc[16];
    {
        ull_t binit[4];
        if (c0 < 64) {
            float4 bv = *(const float4*)&b1[c0];
            DUP(binit[0], bv.x); DUP(binit[1], bv.y);
            DUP(binit[2], bv.z); DUP(binit[3], bv.w);
        } else {
            binit[0] = binit[1] = binit[2] = binit[3] = 0ull;
        }
#pragma unroll
        for (int p = 0; p < 4; ++p)
#pragma unroll
            for (int c = 0; c < 4; ++c) acc[p * 4 + c] = binit[c];
    }

#pragma unroll 4
    for (int k = 0; k < 64; ++k) {
        float4 w = *(const float4*)&Wc[k * 128 + c0];
        ull_t W0, W1r, W2r, W3r;
        DUP(W0, w.x); DUP(W1r, w.y); DUP(W2r, w.z); DUP(W3r, w.w);
        const ull_t* xp = (const ull_t*)&xT[k * 66 + n0];
        ull_t X0 = xp[0], X1 = xp[1], X2 = xp[2], X3 = xp[3];
        fma2(acc[ 0], X0, W0); fma2(acc[ 1], X0, W1r);
        fma2(acc[ 2], X0, W2r); fma2(acc[ 3], X0, W3r);
        fma2(acc[ 4], X1, W0); fma2(acc[ 5], X1, W1r);
        fma2(acc[ 6], X1, W2r); fma2(acc[ 7], X1, W3r);
        fma2(acc[ 8], X2, W0); fma2(acc[ 9], X2, W1r);
        fma2(acc[10], X2, W2r); fma2(acc[11], X2, W3r);
        fma2(acc[12], X3, W0); fma2(acc[13], X3, W1r);
        fma2(acc[14], X3, W2r); fma2(acc[15], X3, W3r);
    }

#pragma unroll
    for (int p = 0; p < 4; ++p) {
        float lo0, hi0, lo1, hi1, lo2, hi2, lo3, hi3;
        UNPK(lo0, hi0, acc[p * 4 + 0]);
        UNPK(lo1, hi1, acc[p * 4 + 1]);
        UNPK(lo2, hi2, acc[p * 4 + 2]);
        UNPK(lo3, hi3, acc[p * 4 + 3]);
        int gn0 = n_base + n0 + 2 * p;
        if (gn0 < N)
            *(float4*)&g_AB[(size_t)gn0 * 128 + c0] = make_float4(lo0, lo1, lo2, lo3);
        if (gn0 + 1 < N)
            *(float4*)&g_AB[(size_t)(gn0 + 1) * 128 + c0] = make_float4(hi0, hi1, hi2, hi3);
    }
}

// ---------------------------------------------------------------------------
// Edge kernel. 128 edges/block, 256 threads, 4ch x 8edge per thread.
// Half-prefetch: pairs 2-3 gathers via cp.async (covered by GEMM1),
// pairs 0-1 direct LDG (R15 path). 3 CTAs/SM retained.
// dyn smem (58880 B):
//   iidx[128] @0, jidx[128] @512
//   W1p [32][64] f32 raw @1024   (8192)
//   eaT [32][132] f32    @9216   (16896)
//   gA  [64][64] f32     @26112  (16384)   prefetched A rows (pairs 2-3)
//   gB  [64][64] f32     @42496  (16384)   prefetched B rows
__global__ void __launch_bounds__(NTHREADS, 3)
edge_kernel(const void* __restrict__ edge_index,
            const float* __restrict__ edge_attr,
            const float* __restrict__ W1,
            const float* __restrict__ gamma,
            const float* __restrict__ beta,
            int E) {
    extern __shared__ char smraw[];
    int*   iidx = (int*)smraw;
    int*   jidx = iidx + 128;
    float* W1p  = (float*)(smraw + 1024);
    float* eaT  = (float*)(smraw + 9216);
    float* gA   = (float*)(smraw + 26112);
    float* gB   = (float*)(smraw + 42496);

    int t = threadIdx.x;
    long long e_base = (long long)blockIdx.x * E_TILE;
    int idx64 = g_idx64;

    if (t < 128) iidx[t] = load_edge_idx(edge_index, e_base + t, idx64);
    else         jidx[t - 128] = load_edge_idx(edge_index, (long long)E + e_base + (t - 128), idx64);

    // W1p: raw copy of W1 rows 128..159 (2048 floats = 512 float4)
    {
        const float4* src = (const float4*)(W1 + 128 * 64);
        float4* dst = (float4*)W1p;
        dst[t]       = src[t];
        dst[t + 256] = src[t + 256];
    }
    // edge_attr transposed: eaT[k][e], stride 132
    {
        const float4* ea4 = (const float4*)edge_attr;
#pragma unroll
        for (int it = 0; it < 4; ++it) {
            int slot = t + it * NTHREADS;           // 0..1023
            int e = slot >> 3, q = slot & 7;
            float4 v = ea4[e_base * 8 + slot];
            int k = q * 4;
            eaT[(k + 0) * 132 + e] = v.x;
            eaT[(k + 1) * 132 + e] = v.y;
            eaT[(k + 2) * 132 + e] = v.z;
            eaT[(k + 3) * 132 + e] = v.w;
        }
    }
    __syncthreads();

    int tx = t & 15, ty = t >> 4;
    int c0 = tx * 4, e0 = ty * 8;

    // -------- prefetch pairs 2-3 gathers (edges e0+4..e0+7) --------
    // compacted slot = ty*4 + (r-4); each thread fetches its own consumption.
    {
        unsigned sA = (unsigned)__cvta_generic_to_shared(gA) + (ty * 4 * 64 + tx * 4) * 4;
        unsigned sB = (unsigned)__cvta_generic_to_shared(gB) + (ty * 4 * 64 + tx * 4) * 4;
#pragma unroll
        for (int r = 4; r < 8; ++r) {
            int e = e0 + r;
            const float* pa = g_AB + (size_t)iidx[e] * 128 + c0;         // A part
            const float* pb = g_AB + (size_t)jidx[e] * 128 + 64 + c0;    // B part
            CP_ASYNC16(sA + (r - 4) * 256, pa);
            CP_ASYNC16(sB + (r - 4) * 256, pb);
        }
        asm volatile("cp.async.commit_group;" ::: "memory");
    }

    // acc[c*4+p]: channel c (0..3), edge-pair p (0..3), lanes = (e0+2p, e0+2p+1)
    ull_t acc[16];
#pragma unroll
    for (int i = 0; i < 16; ++i) acc[i] = 0ull;

    // -------- GEMM1: h = ea @ W1c (raw weight LDS.128 + reg dup) --------
#pragma unroll 4
    for (int kk = 0; kk < 32; ++kk) {
        float4 w = *(const float4*)&W1p[kk * 64 + c0];
        ull_t W0, W1r, W2r, W3r;
        DUP(W0, w.x); DUP(W1r, w.y); DUP(W2r, w.z); DUP(W3r, w.w);
        const float* ap = eaT + kk * 132 + e0;
        ulonglong2 A01 = *(const ulonglong2*)(ap);
        ulonglong2 A23 = *(const ulonglong2*)(ap + 4);
        fma2(acc[ 0], A01.x, W0);  fma2(acc[ 1], A01.y, W0);
        fma2(acc[ 2], A23.x, W0);  fma2(acc[ 3], A23.y, W0);
        fma2(acc[ 4], A01.x, W1r); fma2(acc[ 5], A01.y, W1r);
        fma2(acc[ 6], A23.x, W1r); fma2(acc[ 7], A23.y, W1r);
        fma2(acc[ 8], A01.x, W2r); fma2(acc[ 9], A01.y, W2r);
        fma2(acc[10], A23.x, W2r); fma2(acc[11], A23.y, W2r);
        fma2(acc[12], A01.x, W3r); fma2(acc[13], A01.y, W3r);
        fma2(acc[14], A23.x, W3r); fma2(acc[15], A23.y, W3r);
    }

    // -------- epilogue, pair-by-pair, packed --------
    float4 gmv = *(const float4*)&gamma[c0];
    float4 btv = *(const float4*)&beta[c0];
    ull_t GM0, GM1, GM2, GM3, BT0, BT1, BT2, BT3;
    DUP(GM0, gmv.x); DUP(GM1, gmv.y); DUP(GM2, gmv.z); DUP(GM3, gmv.w);
    DUP(BT0, btv.x); DUP(BT1, btv.y); DUP(BT2, btv.z); DUP(BT3, btv.w);
    const float4* AB4 = (const float4*)g_AB;

#pragma unroll
    for (int p = 0; p < 4; ++p) {
        int ea = e0 + 2 * p, eb = ea + 1;

        float4 Aa, Ba, Ab, Bb;
        if (p < 2) {
            // direct LDG gathers (R15 path)
            Aa = AB4[(size_t)iidx[ea] * 32 + tx];
            Ba = AB4[(size_t)jidx[ea] * 32 + 16 + tx];
            Ab = AB4[(size_t)iidx[eb] * 32 + tx];
            Bb = AB4[(size_t)jidx[eb] * 32 + 16 + tx];
        } else {
            if (p == 2) asm volatile("cp.async.wait_group 0;" ::: "memory");
            int sa0 = ty * 4 + (2 * p - 4);        // slot for edge ea
            Aa = *(const float4*)&gA[sa0 * 64 + c0];
            Ba = *(const float4*)&gB[sa0 * 64 + c0];
            Ab = *(const float4*)&gA[(sa0 + 1) * 64 + c0];
            Bb = *(const float4*)&gB[(sa0 + 1) * 64 + c0];
        }

        ull_t g0, g1, g2, g3;
        PACK2(g0, Aa.x + Ba.x, Ab.x + Bb.x);
        PACK2(g1, Aa.y + Ba.y, Ab.y + Bb.y);
        PACK2(g2, Aa.z + Ba.z, Ab.z + Bb.z);
        PACK2(g3, Aa.w + Ba.w, Ab.w + Bb.w);

        ull_t h0 = add2(acc[0 * 4 + p], g0);
        ull_t h1 = add2(acc[1 * 4 + p], g1);
        ull_t h2 = add2(acc[2 * 4 + p], g2);
        ull_t h3 = add2(acc[3 * 4 + p], g3);

        ull_t s_pk = add2(add2(h0, h1), add2(h2, h3));
        ull_t q_pk = 0ull;
        fma2(q_pk, h0, h0); fma2(q_pk, h1, h1);
        fma2(q_pk, h2, h2); fma2(q_pk, h3, h3);

        float sa, sb, qa, qb;
        UNPK(sa, sb, s_pk);
        UNPK(qa, qb, q_pk);
#pragma unroll
        for (int off = 8; off >= 1; off >>= 1) {
            sa += __shfl_xor_sync(0xffffffffu, sa, off, 16);
            sb += __shfl_xor_sync(0xffffffffu, sb, off, 16);
            qa += __shfl_xor_sync(0xffffffffu, qa, off, 16);
            qb += __shfl_xor_sync(0xffffffffu, qb, off, 16);
        }
        float mua = sa * (1.0f / 64.0f);
        float mub = sb * (1.0f / 64.0f);
        float ra  = rsqrtf(qa * (1.0f / 64.0f) - mua * mua + 1e-5f);
        float rb  = rsqrtf(qb * (1.0f / 64.0f) - mub * mub + 1e-5f);

        ull_t NMU, RR;
        PACK2(NMU, -mua, -mub);
        PACK2(RR, ra, rb);

        ull_t y0 = BT0; fma2(y0, mul2(add2(h0, NMU), RR), GM0);
        ull_t y1 = BT1; fma2(y1, mul2(add2(h1, NMU), RR), GM1);
        ull_t y2 = BT2; fma2(y2, mul2(add2(h2, NMU), RR), GM2);
        ull_t y3 = BT3; fma2(y3, mul2(add2(h3, NMU), RR), GM3);

        float va0, vb0, va1, vb1, va2, vb2, va3, vb3;
        UNPK(va0, vb0, y0);
        UNPK(va1, vb1, y1);
        UNPK(va2, vb2, y2);
        UNPK(va3, vb3, y3);

        va0 = gelu_exact(va0); va1 = gelu_exact(va1);
        va2 = gelu_exact(va2); va3 = gelu_exact(va3);
        vb0 = gelu_exact(vb0); vb1 = gelu_exact(vb1);
        vb2 = gelu_exact(vb2); vb3 = gelu_exact(vb3);

        {
            int vja = jidx[ea];
            float* pa = g_G + (size_t)vja * 64 + c0;
            asm volatile("red.global.add.v4.f32 [%0], {%1,%2,%3,%4};"
                         :: "l"(pa), "f"(va0), "f"(va1), "f"(va2), "f"(va3) : "memory");
            int vjb = jidx[eb];
            float* pb = g_G + (size_t)vjb * 64 + c0;
            asm volatile("red.global.add.v4.f32 [%0], {%1,%2,%3,%4};"
                         :: "l"(pb), "f"(vb0), "f"(vb1), "f"(vb2), "f"(vb3) : "memory");
            if (tx == 0) {
                asm volatile("red.global.add.f32 [%0], %1;"
                             :: "l"(g_degf + vja), "f"(1.0f) : "memory");
                asm volatile("red.global.add.f32 [%0], %1;"
                             :: "l"(g_degf + vjb), "f"(1.0f) : "memory");
            }
        }
    }
}

// ---------------------------------------------------------------------------
// Node kernel (R14 FFMA2, node-pair packing).
// dyn smem: GT[64][66] (16896) + W2s[64][64] (16384) = 33280 B
__global__ void __launch_bounds__(NTHREADS, 2)
node_kernel(const float* __restrict__ W2,
            const float* __restrict__ b2,
            float* __restrict__ out,
            int N) {
    extern __shared__ float sm[];
    float* GT  = sm;                  // [k][node], stride 66
    float* W2s = sm + 64 * 66;        // [k][c] 64x64

    int t = threadIdx.x;
    int n_base = blockIdx.x * 64;

#pragma unroll
    for (int it = 0; it < 16; ++it) {
        int idx = t + it * NTHREADS;
        int node = idx >> 6, k = idx & 63;
        int gn = n_base + node;
        GT[k * 66 + node] = (gn < N) ? g_G[(size_t)gn * 64 + k] : 0.f;
        W2s[idx] = W2[idx];
    }
    __syncthreads();

    int tx = t & 15, ty = t >> 4;
    int c0 = tx * 4, n0 = ty * 4;

    ull_t acc[8];
#pragma unroll
    for (int i = 0; i < 8; ++i) acc[i] = 0ull;

#pragma unroll 4
    for (int k = 0; k < 64; ++k) {
        float4 w = *(const float4*)&W2s[k * 64 + c0];
        ull_t W0, W1r, W2r, W3r;
        DUP(W0, w.x); DUP(W1r, w.y); DUP(W2r, w.z); DUP(W3r, w.w);
        const ull_t* gp = (const ull_t*)&GT[k * 66 + n0];
        ull_t X0 = gp[0], X1 = gp[1];
        fma2(acc[0], X0, W0); fma2(acc[1], X0, W1r);
        fma2(acc[2], X0, W2r); fma2(acc[3], X0, W3r);
        fma2(acc[4], X1, W0); fma2(acc[5], X1, W1r);
        fma2(acc[6], X1, W2r); fma2(acc[7], X1, W3r);
    }

    float4 b2v = *(const float4*)&b2[c0];
    ull_t B0, B1, B2, B3;
    DUP(B0, b2v.x); DUP(B1, b2v.y); DUP(B2, b2v.z); DUP(B3, b2v.w);

#pragma unroll
    for (int p = 0; p < 2; ++p) {
        int gn0 = n_base + n0 + 2 * p;
        float d0 = (gn0 < N)     ? g_degf[gn0]     : 0.f;
        float d1 = (gn0 + 1 < N) ? g_degf[gn0 + 1] : 0.f;
        ull_t D; PACK2(D, d0, d1);
        ull_t v0 = acc[p * 4 + 0], v1 = acc[p * 4 + 1];
        ull_t v2 = acc[p * 4 + 2], v3 = acc[p * 4 + 3];
        fma2(v0, D, B0); fma2(v1, D, B1);
        fma2(v2, D, B2); fma2(v3, D, B3);
        float lo0, hi0, lo1, hi1, lo2, hi2, lo3, hi3;
        UNPK(lo0, hi0, v0); UNPK(lo1, hi1, v1);
        UNPK(lo2, hi2, v2); UNPK(lo3, hi3, v3);
        if (gn0 < N)
            *(float4*)&out[(size_t)gn0 * 64 + c0] = make_float4(lo0, lo1, lo2, lo3);
        if (gn0 + 1 < N)
            *(float4*)&out[(size_t)(gn0 + 1) * 64 + c0] = make_float4(hi0, hi1, hi2, hi3);
    }
}

// ---------------------------------------------------------------------------
extern "C" void kernel_launch(void* const* d_in, const int* in_sizes, int n_in,
                              void* d_out, int out_size) {
    const float* x          = (const float*)d_in[0];
    const void*  edge_index = d_in[1];
    const float* edge_attr  = (const float*)d_in[2];
    const float* W1         = (const float*)d_in[3];
    const float* b1         = (const float*)d_in[4];
    const float* gamma      = (const float*)d_in[5];
    const float* beta       = (const float*)d_in[6];
    const float* W2         = (const float*)d_in[7];
    const float* b2         = (const float*)d_in[8];
    float*       out        = (float*)d_out;

    int N = in_sizes[0] / 64;     // 100000
    int E = in_sizes[2] / 32;     // 1600000

    const int SM_PRE  = (64 * 66 + 64 * 128) * 4;   // 49664
    const int SM_EDGE = 58880;
    const int SM_NODE = (64 * 66 + 64 * 64) * 4;    // 33280
    cudaFuncSetAttribute(precompute_kernel, cudaFuncAttributeMaxDynamicSharedMemorySize, SM_PRE);
    cudaFuncSetAttribute(edge_kernel,       cudaFuncAttributeMaxDynamicSharedMemorySize, SM_EDGE);
    cudaFuncSetAttribute(node_kernel,       cudaFuncAttributeMaxDynamicSharedMemorySize, SM_NODE);

    detect_idx_kernel<<<1, 128>>>(edge_index, N);
    precompute_kernel<<<(N + 63) / 64, NTHREADS, SM_PRE>>>(x, W1, b1, N);
    edge_kernel<<<E / E_TILE, NTHREADS, SM_EDGE>>>(edge_index, edge_attr, W1,
                                                   gamma, beta, E);
    node_kernel<<<(N + 63) / 64, NTHREADS, SM_NODE>>>(W2, b2, out, N);
}